// round 9
// baseline (speedup 1.0000x reference)
#include <cuda_runtime.h>
#include <cuda_fp16.h>
#include <cstdint>

#define N_TOK 8192
#define D_IN  1024
#define D_OUTV 1024
#define NE    8
#define K_TOT 8192
#define K_PAD 8256            // 8192 + 64 (bias fold + zero pad), 129 * 64

#define BM 128
#define BN 128
#define BK 64
#define STAGES 3
#define NIT (K_PAD / BK)      // 129
#define THREADS 256

#define A_STAGE (BM * BK * 2)         // 16384
#define B_STAGE (BN * BK * 2)         // 16384
#define SMEM_BYTES (STAGES * (A_STAGE + B_STAGE))   // 98304 -> 2 CTAs/SM

// ---- scratch (allocation-free device globals) ----
__device__ __align__(1024) __half g_Ah[(size_t)N_TOK * K_PAD];   // A' = gate-scaled x + gate cols
__device__ __align__(1024) __half g_Bh[(size_t)D_OUTV * K_PAD];  // W' [o][k] + bias cols
__device__ float g_gate[N_TOK * NE];

// ============================ PTX helpers ============================
__device__ __forceinline__ uint32_t smem_u32(const void* p) {
    uint32_t a;
    asm("{ .reg .u64 t; cvta.to.shared.u64 t, %1; cvt.u32.u64 %0, t; }" : "=r"(a) : "l"(p));
    return a;
}
__device__ __forceinline__ void cp_async16(uint32_t saddr, const void* gptr) {
    asm volatile("cp.async.cg.shared.global [%0], [%1], 16;\n" :: "r"(saddr), "l"(gptr));
}
__device__ __forceinline__ void cp_commit() {
    asm volatile("cp.async.commit_group;\n");
}
template <int n> __device__ __forceinline__ void cp_wait() {
    asm volatile("cp.async.wait_group %0;\n" :: "n"(n));
}
__device__ __forceinline__ void ldsm4(uint32_t r[4], uint32_t addr) {
    asm volatile("ldmatrix.sync.aligned.m8n8.x4.shared.b16 {%0,%1,%2,%3}, [%4];"
                 : "=r"(r[0]), "=r"(r[1]), "=r"(r[2]), "=r"(r[3]) : "r"(addr));
}
__device__ __forceinline__ void mma16816(float c[4], const uint32_t a[4],
                                         uint32_t b0, uint32_t b1) {
    asm volatile(
        "mma.sync.aligned.m16n8k16.row.col.f32.f16.f16.f32 "
        "{%0,%1,%2,%3}, {%4,%5,%6,%7}, {%8,%9}, {%0,%1,%2,%3};"
        : "+f"(c[0]), "+f"(c[1]), "+f"(c[2]), "+f"(c[3])
        : "r"(a[0]), "r"(a[1]), "r"(a[2]), "r"(a[3]), "r"(b0), "r"(b1));
}

// ============================ prepass kernels ============================
__global__ __launch_bounds__(256) void gate_kernel(const float* __restrict__ x,
                                                   const float* __restrict__ Wg,
                                                   const float* __restrict__ bg) {
    __shared__ float sWg[NE][D_IN];
    int tid = threadIdx.x;
    for (int idx = tid; idx < D_IN * NE; idx += 256) {
        int i = idx >> 3, e = idx & 7;
        sWg[e][i] = Wg[idx];
    }
    __syncthreads();
    int warp = tid >> 5, lane = tid & 31;
    int n = blockIdx.x * 8 + warp;
    const float* xr = x + (size_t)n * D_IN;
    float acc[NE];
#pragma unroll
    for (int e = 0; e < NE; e++) acc[e] = 0.f;
    for (int i = lane; i < D_IN; i += 32) {
        float xv = xr[i];
#pragma unroll
        for (int e = 0; e < NE; e++) acc[e] += xv * sWg[e][i];
    }
#pragma unroll
    for (int e = 0; e < NE; e++)
#pragma unroll
        for (int off = 16; off; off >>= 1)
            acc[e] += __shfl_xor_sync(0xffffffffu, acc[e], off);
    if (lane == 0) {
        float m = -1e30f;
#pragma unroll
        for (int e = 0; e < NE; e++) { acc[e] += bg[e]; m = fmaxf(m, acc[e]); }
        float s = 0.f;
#pragma unroll
        for (int e = 0; e < NE; e++) { acc[e] = expf(acc[e] - m); s += acc[e]; }
        float inv = 1.f / s;
#pragma unroll
        for (int e = 0; e < NE; e++) g_gate[n * NE + e] = acc[e] * inv;
    }
}

// A'[n][e*1024+i] = fp16(g_e * x[n,i]); cols 8192+e = g_e; pad zeros to 8255
__global__ __launch_bounds__(512) void prescale_kernel(const float* __restrict__ x) {
    __shared__ float g[NE];
    int n = blockIdx.x, t = threadIdx.x;
    if (t < NE) g[t] = g_gate[n * NE + t];
    __syncthreads();
    float2 v = reinterpret_cast<const float2*>(x + (size_t)n * D_IN)[t];
    __half* dst = g_Ah + (size_t)n * K_PAD;
#pragma unroll
    for (int e = 0; e < NE; e++) {
        __half2 h = __floats2half2_rn(g[e] * v.x, g[e] * v.y);
        reinterpret_cast<__half2*>(dst + e * D_IN)[t] = h;
    }
    if (t < 32) {   // K extension: 64 cols = 32 half2
        __half2 h = (t < 4) ? __floats2half2_rn(g[2 * t], g[2 * t + 1])
                            : __floats2half2_rn(0.f, 0.f);
        reinterpret_cast<__half2*>(dst + K_TOT)[t] = h;
    }
}

// W'[o][e*1024+i] = fp16(We[e][i][o]) — tiled transpose
__global__ __launch_bounds__(256) void transW_kernel(const float* __restrict__ We) {
    __shared__ float t[32][33];
    int e = blockIdx.z;
    int i0 = blockIdx.y * 32, o0 = blockIdx.x * 32;
    int tx = threadIdx.x, ty = threadIdx.y;
    for (int r = ty; r < 32; r += 8)
        t[r][tx] = We[((size_t)e * D_IN + i0 + r) * D_OUTV + o0 + tx];
    __syncthreads();
    for (int r = ty; r < 32; r += 8)
        g_Bh[(size_t)(o0 + r) * K_PAD + e * D_IN + i0 + tx] = __float2half(t[tx][r]);
}

// B' bias cols: [o][8192+e] = be[e][o], zeros to 8255
__global__ __launch_bounds__(256) void biasB_kernel(const float* __restrict__ be) {
    int idx = blockIdx.x * 256 + threadIdx.x;   // 0 .. 32767
    int o = idx >> 5, j = idx & 31;
    __half2 h = (j < 4) ? __floats2half2_rn(be[(2 * j) * D_OUTV + o],
                                            be[(2 * j + 1) * D_OUTV + o])
                        : __floats2half2_rn(0.f, 0.f);
    reinterpret_cast<__half2*>(g_Bh + (size_t)o * K_PAD + K_TOT)[j] = h;
}

// ============================ main GEMM ============================
__device__ __forceinline__ void load_stage(int kt, int s, int m0, int o0,
                                           uint32_t sA, uint32_t sB, int tid) {
    const int k0 = kt * BK;
#pragma unroll
    for (int j = 0; j < 4; j++) {            // A: 128 rows x 8 chunks = 1024
        int idx = j * 256 + tid;
        int r = idx >> 3, c = idx & 7;
        const void* src = g_Ah + (size_t)(m0 + r) * K_PAD + k0 + c * 8;
        cp_async16(sA + s * A_STAGE + r * 128 + ((c ^ (r & 7)) << 4), src);
    }
#pragma unroll
    for (int j = 0; j < 4; j++) {            // B: 128 rows x 8 chunks = 1024
        int idx = j * 256 + tid;
        int r = idx >> 3, c = idx & 7;
        const void* src = g_Bh + (size_t)(o0 + r) * K_PAD + k0 + c * 8;
        cp_async16(sB + s * B_STAGE + r * 128 + ((c ^ (r & 7)) << 4), src);
    }
}

__global__ __launch_bounds__(THREADS, 2) void moe_gemm_kernel(float* __restrict__ out) {
    extern __shared__ char smem[];
    const uint32_t sA = smem_u32(smem);
    const uint32_t sB = sA + STAGES * A_STAGE;
    const int tid = threadIdx.x, warp = tid >> 5, lane = tid & 31;
    const int wm = warp & 1, wn = warp >> 1;          // 2 (m) x 4 (n) warps
    const int m0 = blockIdx.y * BM;
    const int o0 = blockIdx.x * BN;
    const int lr = lane & 15, lc = lane >> 4;

    float acc[4][4][4];                                // warp tile 64 x 32
#pragma unroll
    for (int mt = 0; mt < 4; mt++)
#pragma unroll
        for (int nt = 0; nt < 4; nt++)
#pragma unroll
            for (int f = 0; f < 4; f++) acc[mt][nt][f] = 0.f;

    load_stage(0, 0, m0, o0, sA, sB, tid); cp_commit();
    load_stage(1, 1, m0, o0, sA, sB, tid); cp_commit();

    int s = 0;
    for (int kt = 0; kt < NIT; kt++) {
        cp_wait<1>();
        __syncthreads();
        if (kt + 2 < NIT) {
            int s2 = s + 2 >= STAGES ? s + 2 - STAGES : s + 2;
            load_stage(kt + 2, s2, m0, o0, sA, sB, tid);
        }
        cp_commit();

        const uint32_t aB = sA + s * A_STAGE;
        const uint32_t bB = sB + s * B_STAGE;
#pragma unroll
        for (int kk = 0; kk < 4; kk++) {
            uint32_t a[4][4], b[2][4];
#pragma unroll
            for (int t = 0; t < 4; t++) {
                int ra = wm * 64 + t * 16 + lr;
                ldsm4(a[t], aB + ra * 128 + (((kk * 2 + lc) ^ (ra & 7)) << 4));
            }
#pragma unroll
            for (int t = 0; t < 2; t++) {
                int rb = wn * 32 + t * 16 + lr;
                ldsm4(b[t], bB + rb * 128 + (((kk * 2 + lc) ^ (rb & 7)) << 4));
            }
#pragma unroll
            for (int mt = 0; mt < 4; mt++)
#pragma unroll
                for (int nt = 0; nt < 4; nt++) {
                    int gidx = nt >> 1, p = nt & 1;
                    mma16816(acc[mt][nt], a[mt], b[gidx][p], b[gidx][p + 2]);
                }
        }
        s = (s + 1 >= STAGES) ? 0 : s + 1;
    }

    // epilogue: direct fp32 stores (bias already folded into K)
#pragma unroll
    for (int mt = 0; mt < 4; mt++) {
        int row0 = m0 + wm * 64 + mt * 16 + (lane >> 2);
#pragma unroll
        for (int nt = 0; nt < 4; nt++) {
            int col = o0 + wn * 32 + nt * 8 + (lane & 3) * 2;
            *reinterpret_cast<float2*>(out + (size_t)row0 * D_OUTV + col) =
                make_float2(acc[mt][nt][0], acc[mt][nt][1]);
            *reinterpret_cast<float2*>(out + (size_t)(row0 + 8) * D_OUTV + col) =
                make_float2(acc[mt][nt][2], acc[mt][nt][3]);
        }
    }
}

// ============================ host launch ============================
extern "C" void kernel_launch(void* const* d_in, const int* in_sizes, int n_in,
                              void* d_out, int out_size) {
    const float* x  = (const float*)d_in[0];
    const float* We = (const float*)d_in[1];
    const float* be = (const float*)d_in[2];
    const float* Wg = (const float*)d_in[3];
    const float* bg = (const float*)d_in[4];
    float* out = (float*)d_out;

    cudaFuncSetAttribute(moe_gemm_kernel,
                         cudaFuncAttributeMaxDynamicSharedMemorySize, SMEM_BYTES);

    gate_kernel<<<N_TOK / 8, 256>>>(x, Wg, bg);
    prescale_kernel<<<N_TOK, 512>>>(x);
    transW_kernel<<<dim3(32, 32, 8), dim3(32, 8)>>>(We);
    biasB_kernel<<<128, 256>>>(be);

    dim3 grid(D_OUTV / BN, N_TOK / BM);   // (8, 64) = 512 blocks, 2 per SM
    moe_gemm_kernel<<<grid, THREADS, SMEM_BYTES>>>(out);
}

// round 14
// speedup vs baseline: 1.0318x; 1.0318x over previous
#include <cuda_runtime.h>
#include <cuda_fp16.h>
#include <cstdint>
#include <cstdio>
#include <cstring>
#include <dlfcn.h>
#include <unistd.h>
#include <sys/wait.h>

#define N_TOK 8192
#define D_IN  1024
#define D_OUTV 1024
#define NE    8
#define K_TOT 8192
#define K_PAD 8256            // 8192 + 64 (bias fold + zero pad), 129 * 64

// ---------------- fallback mma.sync GEMM config (R8, proven 471us) ----------
#define BM 128
#define BN 256
#define BK 64
#define STAGES 4
#define NIT (K_PAD / BK)      // 129
#define THREADS 512
#define A_STAGE (BM * BK * 2)         // 16384
#define B_STAGE (BN * BK * 2)         // 32768
#define SMEM_BYTES (STAGES * (A_STAGE + B_STAGE))   // 196608

// ---------------- tcgen05 JIT kernel config ----------------
// smem: [0,1024) ctrl | A: 1024 + s*16384 (2 x 16KB) | B: 33792 + s*32768 (2 x 32KB)
#define TC_SMEM 99328

// ---- scratch (allocation-free device globals) ----
__device__ __align__(1024) __half g_Ah[(size_t)N_TOK * K_PAD];   // A' = gate-scaled x + gate cols
__device__ __align__(1024) __half g_Bh[(size_t)D_OUTV * K_PAD];  // W' [o][k] + bias cols
__device__ float g_gate[N_TOK * NE];

// ============================ PTX helpers (fallback) ============================
__device__ __forceinline__ uint32_t smem_u32(const void* p) {
    uint32_t a;
    asm("{ .reg .u64 t; cvta.to.shared.u64 t, %1; cvt.u32.u64 %0, t; }" : "=r"(a) : "l"(p));
    return a;
}
__device__ __forceinline__ void cp_async16(uint32_t saddr, const void* gptr) {
    asm volatile("cp.async.cg.shared.global [%0], [%1], 16;\n" :: "r"(saddr), "l"(gptr));
}
__device__ __forceinline__ void cp_commit() {
    asm volatile("cp.async.commit_group;\n");
}
template <int n> __device__ __forceinline__ void cp_wait() {
    asm volatile("cp.async.wait_group %0;\n" :: "n"(n));
}
__device__ __forceinline__ void ldsm4(uint32_t r[4], uint32_t addr) {
    asm volatile("ldmatrix.sync.aligned.m8n8.x4.shared.b16 {%0,%1,%2,%3}, [%4];"
                 : "=r"(r[0]), "=r"(r[1]), "=r"(r[2]), "=r"(r[3]) : "r"(addr));
}
__device__ __forceinline__ void mma16816(float c[4], const uint32_t a[4],
                                         uint32_t b0, uint32_t b1) {
    asm volatile(
        "mma.sync.aligned.m16n8k16.row.col.f32.f16.f16.f32 "
        "{%0,%1,%2,%3}, {%4,%5,%6,%7}, {%8,%9}, {%0,%1,%2,%3};"
        : "+f"(c[0]), "+f"(c[1]), "+f"(c[2]), "+f"(c[3])
        : "r"(a[0]), "r"(a[1]), "r"(a[2]), "r"(a[3]), "r"(b0), "r"(b1));
}

// ============================ prepass kernels ============================
__global__ __launch_bounds__(256) void gate_kernel(const float* __restrict__ x,
                                                   const float* __restrict__ Wg,
                                                   const float* __restrict__ bg) {
    __shared__ float sWg[NE][D_IN];
    int tid = threadIdx.x;
    for (int idx = tid; idx < D_IN * NE; idx += 256) {
        int i = idx >> 3, e = idx & 7;
        sWg[e][i] = Wg[idx];
    }
    __syncthreads();
    int warp = tid >> 5, lane = tid & 31;
    int n = blockIdx.x * 8 + warp;
    const float* xr = x + (size_t)n * D_IN;
    float acc[NE];
#pragma unroll
    for (int e = 0; e < NE; e++) acc[e] = 0.f;
    for (int i = lane; i < D_IN; i += 32) {
        float xv = xr[i];
#pragma unroll
        for (int e = 0; e < NE; e++) acc[e] += xv * sWg[e][i];
    }
#pragma unroll
    for (int e = 0; e < NE; e++)
#pragma unroll
        for (int off = 16; off; off >>= 1)
            acc[e] += __shfl_xor_sync(0xffffffffu, acc[e], off);
    if (lane == 0) {
        float m = -1e30f;
#pragma unroll
        for (int e = 0; e < NE; e++) { acc[e] += bg[e]; m = fmaxf(m, acc[e]); }
        float s = 0.f;
#pragma unroll
        for (int e = 0; e < NE; e++) { acc[e] = expf(acc[e] - m); s += acc[e]; }
        float inv = 1.f / s;
#pragma unroll
        for (int e = 0; e < NE; e++) g_gate[n * NE + e] = acc[e] * inv;
    }
}

// A'[n][e*1024+i] = fp16(g_e * x[n,i]); cols 8192+e = g_e; pad zeros to 8255
__global__ __launch_bounds__(512) void prescale_kernel(const float* __restrict__ x) {
    __shared__ float g[NE];
    int n = blockIdx.x, t = threadIdx.x;
    if (t < NE) g[t] = g_gate[n * NE + t];
    __syncthreads();
    float2 v = reinterpret_cast<const float2*>(x + (size_t)n * D_IN)[t];
    __half* dst = g_Ah + (size_t)n * K_PAD;
#pragma unroll
    for (int e = 0; e < NE; e++) {
        __half2 h = __floats2half2_rn(g[e] * v.x, g[e] * v.y);
        reinterpret_cast<__half2*>(dst + e * D_IN)[t] = h;
    }
    if (t < 32) {   // K extension: 64 cols = 32 half2
        __half2 h = (t < 4) ? __floats2half2_rn(g[2 * t], g[2 * t + 1])
                            : __floats2half2_rn(0.f, 0.f);
        reinterpret_cast<__half2*>(dst + K_TOT)[t] = h;
    }
}

// W'[o][e*1024+i] = fp16(We[e][i][o]) — tiled transpose
__global__ __launch_bounds__(256) void transW_kernel(const float* __restrict__ We) {
    __shared__ float t[32][33];
    int e = blockIdx.z;
    int i0 = blockIdx.y * 32, o0 = blockIdx.x * 32;
    int tx = threadIdx.x, ty = threadIdx.y;
    for (int r = ty; r < 32; r += 8)
        t[r][tx] = We[((size_t)e * D_IN + i0 + r) * D_OUTV + o0 + tx];
    __syncthreads();
    for (int r = ty; r < 32; r += 8)
        g_Bh[(size_t)(o0 + r) * K_PAD + e * D_IN + i0 + tx] = __float2half(t[tx][r]);
}

// B' bias cols: [o][8192+e] = be[e][o], zeros to 8255
__global__ __launch_bounds__(256) void biasB_kernel(const float* __restrict__ be) {
    int idx = blockIdx.x * 256 + threadIdx.x;   // 0 .. 32767
    int o = idx >> 5, j = idx & 31;
    __half2 h = (j < 4) ? __floats2half2_rn(be[(2 * j) * D_OUTV + o],
                                            be[(2 * j + 1) * D_OUTV + o])
                        : __floats2half2_rn(0.f, 0.f);
    reinterpret_cast<__half2*>(g_Bh + (size_t)o * K_PAD + K_TOT)[j] = h;
}

// ============================ fallback GEMM (R8) ============================
__device__ __forceinline__ void load_stage(int kt, int s, int m0, int o0,
                                           uint32_t sA, uint32_t sB, int tid) {
    const int k0 = kt * BK;
#pragma unroll
    for (int j = 0; j < 2; j++) {
        int idx = j * 512 + tid;
        int r = idx >> 3, c = idx & 7;
        const void* src = g_Ah + (size_t)(m0 + r) * K_PAD + k0 + c * 8;
        cp_async16(sA + s * A_STAGE + r * 128 + ((c ^ (r & 7)) << 4), src);
    }
#pragma unroll
    for (int j = 0; j < 4; j++) {
        int idx = j * 512 + tid;
        int r = idx >> 3, c = idx & 7;
        const void* src = g_Bh + (size_t)(o0 + r) * K_PAD + k0 + c * 8;
        cp_async16(sB + s * B_STAGE + r * 128 + ((c ^ (r & 7)) << 4), src);
    }
}

__global__ __launch_bounds__(THREADS, 1) void moe_gemm_kernel(float* __restrict__ out) {
    extern __shared__ char smem[];
    const uint32_t sA = smem_u32(smem);
    const uint32_t sB = sA + STAGES * A_STAGE;
    const int tid = threadIdx.x, warp = tid >> 5, lane = tid & 31;
    const int wm = warp & 3, wn = warp >> 2;
    const int m0 = blockIdx.y * BM;
    const int o0 = blockIdx.x * BN;
    const int lr = lane & 15, lc = lane >> 4;

    float acc[2][8][4];
#pragma unroll
    for (int mt = 0; mt < 2; mt++)
#pragma unroll
        for (int nt = 0; nt < 8; nt++)
#pragma unroll
            for (int f = 0; f < 4; f++) acc[mt][nt][f] = 0.f;

    load_stage(0, 0, m0, o0, sA, sB, tid); cp_commit();
    load_stage(1, 1, m0, o0, sA, sB, tid); cp_commit();
    load_stage(2, 2, m0, o0, sA, sB, tid); cp_commit();

    int s = 0;
    for (int kt = 0; kt < NIT; kt++) {
        cp_wait<2>();
        __syncthreads();
        if (kt + 3 < NIT) {
            int s3 = s + 3 >= STAGES ? s + 3 - STAGES : s + 3;
            load_stage(kt + 3, s3, m0, o0, sA, sB, tid);
        }
        cp_commit();

        const uint32_t aB = sA + s * A_STAGE;
        const uint32_t bB = sB + s * B_STAGE;
#pragma unroll
        for (int kk = 0; kk < 4; kk++) {
            uint32_t a[2][4], b[4][4];
#pragma unroll
            for (int t = 0; t < 2; t++) {
                int ra = wm * 32 + t * 16 + lr;
                ldsm4(a[t], aB + ra * 128 + (((kk * 2 + lc) ^ (ra & 7)) << 4));
            }
#pragma unroll
            for (int t = 0; t < 4; t++) {
                int rb = wn * 64 + t * 16 + lr;
                ldsm4(b[t], bB + rb * 128 + (((kk * 2 + lc) ^ (rb & 7)) << 4));
            }
#pragma unroll
            for (int mt = 0; mt < 2; mt++)
#pragma unroll
                for (int nt = 0; nt < 8; nt++) {
                    int gidx = nt >> 1, p = nt & 1;
                    mma16816(acc[mt][nt], a[mt], b[gidx][p], b[gidx][p + 2]);
                }
        }
        s = (s + 1 >= STAGES) ? 0 : s + 1;
    }

#pragma unroll
    for (int mt = 0; mt < 2; mt++) {
        int row0 = m0 + wm * 32 + mt * 16 + (lane >> 2);
#pragma unroll
        for (int nt = 0; nt < 8; nt++) {
            int col = o0 + wn * 64 + nt * 8 + (lane & 3) * 2;
            *reinterpret_cast<float2*>(out + (size_t)row0 * D_OUTV + col) =
                make_float2(acc[mt][nt][0], acc[mt][nt][1]);
            *reinterpret_cast<float2*>(out + (size_t)(row0 + 8) * D_OUTV + col) =
                make_float2(acc[mt][nt][2], acc[mt][nt][3]);
        }
    }
}

// ============================ NVRTC tcgen05 kernel ============================
// Minimal example-shaped config: 128 threads, M=128, N=256, BK=64, 2-stage
// cp.async ring (wait_group 0), tcgen05.fence::before/after around barriers.
// SELFTEST adds module-global scratch tensors (child process only).
static const char* TC_SRC = R"___(
typedef unsigned int u32;
typedef unsigned long long u64;

#ifdef SELFTEST
__device__ char tAg[8192ULL * 16512ULL];
__device__ char tBg[1024ULL * 16512ULL];
__device__ float tOut[8192ULL * 1024ULL];
#endif

__device__ __forceinline__ u32 s2u(const void* p) {
    u32 a;
    asm("{ .reg .u64 t; cvta.to.shared.u64 t, %1; cvt.u32.u64 %0, t; }" : "=r"(a) : "l"(p));
    return a;
}
__device__ __forceinline__ u32 elect1() {
    u32 p;
    asm volatile("{\n\t.reg .pred p;\n\telect.sync _|p, 0xFFFFFFFF;\n\tselp.b32 %0, 1, 0, p;\n\t}" : "=r"(p));
    return p;
}
__device__ __forceinline__ void mwait(u32 m, u32 p) {
    asm volatile(
        "{\n\t.reg .pred P;\n\t"
        "LW_%=:\n\t"
        "mbarrier.try_wait.parity.acquire.cta.shared::cta.b64 P, [%0], %1, 0x989680;\n\t"
        "@P bra LD_%=;\n\t"
        "bra LW_%=;\n\t"
        "LD_%=:\n\t}"
        :: "r"(m), "r"(p) : "memory");
}
__device__ __forceinline__ void cpa(u32 d, const void* s) {
    asm volatile("cp.async.cg.shared.global [%0], [%1], 16;" :: "r"(d), "l"(s));
}
__device__ __forceinline__ u64 mkdesc(u32 a) {
    return (2ULL << 61) | (1ULL << 46) | (64ULL << 32) | (1ULL << 16) |
           ((u64)(a >> 4) & 0x3FFF);
}
__device__ __forceinline__ void mma_f16(u32 d, u64 ad, u64 bd, u32 id, u32 en) {
    asm volatile(
        "{\n\t.reg .pred p;\n\tsetp.ne.u32 p, %4, 0;\n\t"
        "tcgen05.mma.cta_group::1.kind::f16 [%0], %1, %2, %3, {%5,%5,%5,%5}, p;\n\t}"
        :: "r"(d), "l"(ad), "l"(bd), "r"(id), "r"(en), "r"(0u) : "memory");
}

#define ASOFF(s) (1024 + (s) * 16384)
#define BSOFF(s) (33792 + (s) * 32768)

__device__ __forceinline__ void fill(const char* Ag, const char* Bg, u32 sb,
                                     int m0, int o0, int kt, int s, int tid) {
    u64 kb = (u64)kt * 128;
#pragma unroll
    for (int j = 0; j < 8; j++) {          // A: 128 rows x 8 x 16B
        int idx = j * 128 + tid;
        int r = idx >> 3, c = idx & 7;
        cpa(sb + ASOFF(s) + r * 128 + ((c ^ (r & 7)) << 4),
            Ag + (u64)(m0 + r) * 16512 + kb + c * 16);
    }
#pragma unroll
    for (int j = 0; j < 16; j++) {         // B: 256 rows x 8 x 16B
        int idx = j * 128 + tid;
        int r = idx >> 3, c = idx & 7;
        cpa(sb + BSOFF(s) + r * 128 + ((c ^ (r & 7)) << 4),
            Bg + (u64)(o0 + r) * 16512 + kb + c * 16);
    }
    asm volatile("cp.async.commit_group;");
}

extern "C" __global__ void __launch_bounds__(128, 1)
tc_gemm(const char* Ag, const char* Bg, float* out) {
    extern __shared__ char smem[];
    u32 sb = s2u(smem);
    const int tid = threadIdx.x, warp = tid >> 5, lane = tid & 31;
    const int m0 = blockIdx.y * 128, o0 = blockIdx.x * 256;

    if (warp == 0) {
        u32 nc = 512;
        asm volatile("tcgen05.alloc.cta_group::1.sync.aligned.shared::cta.b32 [%0], %1;"
                     :: "r"(sb), "r"(nc) : "memory");
    } else {
        asm volatile("tcgen05.relinquish_alloc_permit.cta_group::1.sync.aligned;");
    }
    if (tid == 0) {
        u32 one = 1;
        asm volatile("mbarrier.init.shared.b64 [%0], %1;" :: "r"(sb + 16), "r"(one) : "memory");
        asm volatile("mbarrier.init.shared.b64 [%0], %1;" :: "r"(sb + 24), "r"(one) : "memory");
    }
    __syncthreads();
    u32 tmem;
    asm volatile("ld.shared.b32 %0, [%1];" : "=r"(tmem) : "r"(sb));

    u32 ph0 = 0, ph1 = 0;
    fill(Ag, Bg, sb, m0, o0, 0, 0, tid);

    const u32 idesc = (1u << 4) | (32u << 17) | (8u << 24);   // f32 acc, f16 in, N=256, M=128
    for (int kt = 0; kt <= 128; kt++) {
        int s = kt & 1;
        asm volatile("cp.async.wait_group 0;" ::: "memory");
        asm volatile("fence.proxy.async.shared::cta;" ::: "memory");
        asm volatile("tcgen05.fence::before_thread_sync;" ::: "memory");
        __syncthreads();
        asm volatile("tcgen05.fence::after_thread_sync;" ::: "memory");
        if (warp == 0) {
            if (elect1()) {
                u64 ad = mkdesc(sb + ASOFF(s));
                u64 bd = mkdesc(sb + BSOFF(s));
#pragma unroll
                for (int k = 0; k < 4; k++) {
                    u32 en = (u32)((kt | k) != 0);
                    mma_f16(tmem, ad + 2 * k, bd + 2 * k, idesc, en);
                }
                asm volatile(
                    "tcgen05.commit.cta_group::1.mbarrier::arrive::one.shared::cluster.b64 [%0];"
                    :: "r"(sb + 16 + 8 * s) : "memory");
            }
        }
        if (kt < 128) {
            int sn = s ^ 1;
            if (kt >= 1) {                 // stage sn was read by mma of tile kt-1
                if (sn) { mwait(sb + 24, ph1); ph1 ^= 1; }
                else    { mwait(sb + 16, ph0); ph0 ^= 1; }
            }
            fill(Ag, Bg, sb, m0, o0, kt + 1, sn, tid);
        }
    }

    mwait(sb + 16, ph0);                   // tile 128 committed on mbar0
    asm volatile("tcgen05.fence::after_thread_sync;" ::: "memory");

    const int row = m0 + warp * 32 + lane;
    float* orow = out + (u64)row * 1024 + o0;
#pragma unroll 1
    for (int ch = 0; ch < 8; ch++) {
        u32 d[32];
        asm volatile(
            "tcgen05.ld.sync.aligned.32x32b.x32.b32 "
            "{%0,%1,%2,%3,%4,%5,%6,%7,%8,%9,%10,%11,%12,%13,%14,%15,"
            "%16,%17,%18,%19,%20,%21,%22,%23,%24,%25,%26,%27,%28,%29,%30,%31}, [%32];"
            : "=r"(d[0]), "=r"(d[1]), "=r"(d[2]), "=r"(d[3]),
              "=r"(d[4]), "=r"(d[5]), "=r"(d[6]), "=r"(d[7]),
              "=r"(d[8]), "=r"(d[9]), "=r"(d[10]), "=r"(d[11]),
              "=r"(d[12]), "=r"(d[13]), "=r"(d[14]), "=r"(d[15]),
              "=r"(d[16]), "=r"(d[17]), "=r"(d[18]), "=r"(d[19]),
              "=r"(d[20]), "=r"(d[21]), "=r"(d[22]), "=r"(d[23]),
              "=r"(d[24]), "=r"(d[25]), "=r"(d[26]), "=r"(d[27]),
              "=r"(d[28]), "=r"(d[29]), "=r"(d[30]), "=r"(d[31])
            : "r"(tmem + ch * 32));
        asm volatile("tcgen05.wait::ld.sync.aligned;" ::: "memory");
#pragma unroll
        for (int q = 0; q < 8; q++) {
            asm volatile("st.global.v4.b32 [%0], {%1,%2,%3,%4};"
                         :: "l"(orow + ch * 32 + q * 4),
                            "r"(d[q * 4 + 0]), "r"(d[q * 4 + 1]),
                            "r"(d[q * 4 + 2]), "r"(d[q * 4 + 3]) : "memory");
        }
    }
    asm volatile("tcgen05.fence::before_thread_sync;" ::: "memory");
    __syncthreads();
    if (tid == 0) {
        asm volatile("mbarrier.inval.shared.b64 [%0];" :: "r"(sb + 16) : "memory");
        asm volatile("mbarrier.inval.shared.b64 [%0];" :: "r"(sb + 24) : "memory");
    }
    __syncthreads();
    if (warp == 0) {
        u32 nc = 512;
        asm volatile("tcgen05.dealloc.cta_group::1.sync.aligned.b32 %0, %1;"
                     :: "r"(tmem), "r"(nc));
    }
}
)___";

// ============================ JIT plumbing ============================
typedef int CUresult_;
typedef int CUdevice_;
typedef void* CUcontext_;
typedef void* CUmodule_;
typedef void* CUfunction_;
typedef void* CUstream_;
typedef unsigned long long CUdeviceptr_;
typedef CUresult_ (*pfn_cuInit)(unsigned);
typedef CUresult_ (*pfn_cuDeviceGet)(CUdevice_*, int);
typedef CUresult_ (*pfn_cuDevicePrimaryCtxRetain)(CUcontext_*, CUdevice_);
typedef CUresult_ (*pfn_cuCtxSetCurrent)(CUcontext_);
typedef CUresult_ (*pfn_cuCtxSynchronize)(void);
typedef CUresult_ (*pfn_cuModuleLoadDataEx)(CUmodule_*, const void*, unsigned, int*, void**);
typedef CUresult_ (*pfn_cuModuleGetFunction)(CUfunction_*, CUmodule_, const char*);
typedef CUresult_ (*pfn_cuModuleGetGlobal)(CUdeviceptr_*, size_t*, CUmodule_, const char*);
typedef CUresult_ (*pfn_cuFuncSetAttribute)(CUfunction_, int, int);
typedef CUresult_ (*pfn_cuLaunchKernel)(CUfunction_, unsigned, unsigned, unsigned,
                                        unsigned, unsigned, unsigned,
                                        unsigned, CUstream_, void**, void**);
typedef int (*pfn_nvrtcCreateProgram)(void**, const char*, const char*, int,
                                      const char* const*, const char* const*);
typedef int (*pfn_nvrtcCompileProgram)(void*, int, const char* const*);
typedef int (*pfn_nvrtcGetCUBINSize)(void*, size_t*);
typedef int (*pfn_nvrtcGetCUBIN)(void*, char*);

static pfn_cuInit p_cuInit;
static pfn_cuDeviceGet p_cuDeviceGet;
static pfn_cuDevicePrimaryCtxRetain p_cuPCR;
static pfn_cuCtxSetCurrent p_cuCtxSetCurrent;
static pfn_cuCtxSynchronize p_cuCtxSync;
static pfn_cuModuleLoadDataEx p_cuMLD;
static pfn_cuModuleGetFunction p_cuMGF;
static pfn_cuModuleGetGlobal p_cuMGG;
static pfn_cuFuncSetAttribute p_cuFSA;
static pfn_cuLaunchKernel p_cuLK;
static pfn_nvrtcCreateProgram p_nvCreate;
static pfn_nvrtcCompileProgram p_nvCompile;
static pfn_nvrtcGetCUBINSize p_nvCubinSize;
static pfn_nvrtcGetCUBIN p_nvCubin;

static CUfunction_ g_tcf = nullptr;
static void* g_pA = nullptr;
static void* g_pB = nullptr;
#define CU_STREAM_LEGACY_ ((CUstream_)0x1)

static bool load_libs() {
    void* hc = dlopen("libcuda.so.1", RTLD_NOW | RTLD_GLOBAL);
    if (!hc) hc = dlopen("libcuda.so", RTLD_NOW | RTLD_GLOBAL);
    if (!hc) return false;
    p_cuInit = (pfn_cuInit)dlsym(hc, "cuInit");
    p_cuDeviceGet = (pfn_cuDeviceGet)dlsym(hc, "cuDeviceGet");
    p_cuPCR = (pfn_cuDevicePrimaryCtxRetain)dlsym(hc, "cuDevicePrimaryCtxRetain");
    p_cuCtxSetCurrent = (pfn_cuCtxSetCurrent)dlsym(hc, "cuCtxSetCurrent");
    p_cuCtxSync = (pfn_cuCtxSynchronize)dlsym(hc, "cuCtxSynchronize");
    p_cuMLD = (pfn_cuModuleLoadDataEx)dlsym(hc, "cuModuleLoadDataEx");
    p_cuMGF = (pfn_cuModuleGetFunction)dlsym(hc, "cuModuleGetFunction");
    p_cuMGG = (pfn_cuModuleGetGlobal)dlsym(hc, "cuModuleGetGlobal");
    p_cuFSA = (pfn_cuFuncSetAttribute)dlsym(hc, "cuFuncSetAttribute");
    p_cuLK = (pfn_cuLaunchKernel)dlsym(hc, "cuLaunchKernel");
    if (!p_cuInit || !p_cuDeviceGet || !p_cuPCR || !p_cuCtxSetCurrent || !p_cuCtxSync ||
        !p_cuMLD || !p_cuMGF || !p_cuMGG || !p_cuFSA || !p_cuLK) return false;
    void* hn = dlopen("libnvrtc.so.13", RTLD_NOW);
    if (!hn) hn = dlopen("libnvrtc.so.12", RTLD_NOW);
    if (!hn) hn = dlopen("libnvrtc.so", RTLD_NOW);
    if (!hn) return false;
    p_nvCreate = (pfn_nvrtcCreateProgram)dlsym(hn, "nvrtcCreateProgram");
    p_nvCompile = (pfn_nvrtcCompileProgram)dlsym(hn, "nvrtcCompileProgram");
    p_nvCubinSize = (pfn_nvrtcGetCUBINSize)dlsym(hn, "nvrtcGetCUBINSize");
    p_nvCubin = (pfn_nvrtcGetCUBIN)dlsym(hn, "nvrtcGetCUBIN");
    return p_nvCreate && p_nvCompile && p_nvCubinSize && p_nvCubin;
}

static bool cu_ready() {
    if (p_cuInit(0) != 0) return false;
    CUdevice_ dev;
    if (p_cuDeviceGet(&dev, 0) != 0) return false;
    CUcontext_ ctx;
    if (p_cuPCR(&ctx, dev) != 0) return false;
    return p_cuCtxSetCurrent(ctx) == 0;
}

static CUmodule_ jit_module(bool selftest) {
    void* prog = nullptr;
    if (p_nvCreate(&prog, TC_SRC, "tc.cu", 0, nullptr, nullptr) != 0) return nullptr;
    const char* opts[2] = {"--gpu-architecture=sm_103a", "-DSELFTEST"};
    if (p_nvCompile(prog, selftest ? 2 : 1, opts) != 0) return nullptr;
    size_t sz = 0;
    if (p_nvCubinSize(prog, &sz) != 0 || sz == 0) return nullptr;
    char* buf = new char[sz];
    if (p_nvCubin(prog, buf) != 0) return nullptr;
    CUmodule_ mod = nullptr;
    if (p_cuMLD(&mod, buf, 0, nullptr, nullptr) != 0) return nullptr;
    return mod;
}

__attribute__((constructor))
static void tc_init() {
    // 1. Fork BEFORE any CUDA activity in this process. The child proves the
    //    tc kernel runs fault-free in its own context; a crash there cannot
    //    touch the parent's (harness's) CUDA state.
    pid_t pid = fork();
    if (pid < 0) return;                 // no fork -> fallback path
    if (pid == 0) {
        // ---------------- child: isolated full-size self-test ----------------
        if (!load_libs() || !cu_ready()) _exit(2);
        CUmodule_ mod = jit_module(true);
        if (!mod) _exit(3);
        CUfunction_ f = nullptr;
        if (p_cuMGF(&f, mod, "tc_gemm") != 0) _exit(4);
        if (p_cuFSA(f, 8 /*MAX_DYNAMIC_SHARED_SIZE_BYTES*/, TC_SMEM) != 0) _exit(5);
        CUdeviceptr_ dA = 0, dB = 0, dO = 0;
        size_t sA, sB, sO;
        if (p_cuMGG(&dA, &sA, mod, "tAg") != 0 ||
            p_cuMGG(&dB, &sB, mod, "tBg") != 0 ||
            p_cuMGG(&dO, &sO, mod, "tOut") != 0) _exit(6);
        void* args[3] = {&dA, &dB, &dO};
        if (p_cuLK(f, 4, 64, 1, 128, 1, 1, TC_SMEM, CU_STREAM_LEGACY_,
                   args, nullptr) != 0) _exit(7);
        _exit(p_cuCtxSync() == 0 ? 0 : 8);
    }
    // ---------------- parent ----------------
    int st = 0;
    if (waitpid(pid, &st, 0) != pid) return;
    if (!WIFEXITED(st) || WEXITSTATUS(st) != 0) return;   // kernel unsafe -> fallback

    // Child proved the kernel. Now do only the proven-benign ops in-process.
    if (!load_libs() || !cu_ready()) return;
    CUmodule_ mod = jit_module(false);
    if (!mod) return;
    CUfunction_ f = nullptr;
    if (p_cuMGF(&f, mod, "tc_gemm") != 0) return;
    if (p_cuFSA(f, 8, TC_SMEM) != 0) return;
    void *pA = nullptr, *pB = nullptr;
    if (cudaGetSymbolAddress(&pA, g_Ah) != cudaSuccess ||
        cudaGetSymbolAddress(&pB, g_Bh) != cudaSuccess) return;
    g_pA = pA;
    g_pB = pB;
    g_tcf = f;
}

// ============================ host launch ============================
extern "C" void kernel_launch(void* const* d_in, const int* in_sizes, int n_in,
                              void* d_out, int out_size) {
    const float* x  = (const float*)d_in[0];
    const float* We = (const float*)d_in[1];
    const float* be = (const float*)d_in[2];
    const float* Wg = (const float*)d_in[3];
    const float* bg = (const float*)d_in[4];
    float* out = (float*)d_out;

    gate_kernel<<<N_TOK / 8, 256>>>(x, Wg, bg);
    prescale_kernel<<<N_TOK, 512>>>(x);
    transW_kernel<<<dim3(32, 32, 8), dim3(32, 8)>>>(We);
    biasB_kernel<<<128, 256>>>(be);

    if (g_tcf) {
        void* args[3] = {&g_pA, &g_pB, &out};
        p_cuLK(g_tcf, 4, 64, 1, 128, 1, 1, TC_SMEM, CU_STREAM_LEGACY_,
               args, nullptr);
    } else {
        cudaFuncSetAttribute(moe_gemm_kernel,
                             cudaFuncAttributeMaxDynamicSharedMemorySize, SMEM_BYTES);
        dim3 grid(D_OUTV / BN, N_TOK / BM);   // (4, 64)
        moe_gemm_kernel<<<grid, THREADS, SMEM_BYTES>>>(out);
    }
}